// round 3
// baseline (speedup 1.0000x reference)
#include <cuda_runtime.h>
#include <math.h>

// Problem constants
#define Bsz 8
#define Lseq 4096
#define Hdim 512
#define N2 32
#define HN (Hdim * N2)

typedef unsigned long long u64;

// ---------------------------------------------------------------------------
// Packed f32x2 helpers (Blackwell sm_103a)
// ---------------------------------------------------------------------------
__device__ __forceinline__ u64 pk2(float lo, float hi) {
    u64 r;
    asm("mov.b64 %0, {%1, %2};" : "=l"(r) : "f"(lo), "f"(hi));
    return r;
}
__device__ __forceinline__ float2 upk2(u64 v) {
    float2 f;
    asm("mov.b64 {%0, %1}, %2;" : "=f"(f.x), "=f"(f.y) : "l"(v));
    return f;
}
__device__ __forceinline__ u64 fma2(u64 a, u64 b, u64 c) {
    u64 d;
    asm("fma.rn.f32x2 %0, %1, %2, %3;" : "=l"(d) : "l"(a), "l"(b), "l"(c));
    return d;
}
__device__ __forceinline__ u64 mul2(u64 a, u64 b) {
    u64 d;
    asm("mul.rn.f32x2 %0, %1, %2;" : "=l"(d) : "l"(a), "l"(b));
    return d;
}

// ---------------------------------------------------------------------------
// Precomputed discretized parameters (per (h, n))
// ---------------------------------------------------------------------------
__device__ float g_dAre[HN];
__device__ float g_dAim[HN];
__device__ float g_dBre[HN];
__device__ float g_dBim[HN];
__device__ float g_C2re[HN];   //  2 * C_re
__device__ float g_C2imN[HN];  // -2 * C_im

// ZOH discretization: dA = exp(dt*A), dB = B * expm1(dt*A)/A
__global__ void s4d_precompute(const float* __restrict__ log_dt,
                               const float* __restrict__ arl,
                               const float* __restrict__ aim,
                               const float* __restrict__ Bre,
                               const float* __restrict__ Bim,
                               const float* __restrict__ Cre,
                               const float* __restrict__ Cim) {
    int i = blockIdx.x * blockDim.x + threadIdx.x;
    if (i >= HN) return;
    int h = i / N2;
    float dt   = expf(log_dt[h]);
    float are  = -expf(arl[i]);
    float aimv = aim[i];
    float zre = are * dt;
    float zim = aimv * dt;
    float sz, cz;
    sincosf(zim, &sz, &cz);
    float ez = expf(zre);
    // dA = e^{z}
    g_dAre[i] = ez * cz;
    g_dAim[i] = ez * sz;
    // expm1(z) = expm1(zre)*cos(zim) - 2 sin^2(zim/2)  + i * e^{zre} sin(zim)
    float sh = sinf(0.5f * zim);
    float em1re = expm1f(zre) * cz - 2.0f * sh * sh;
    float em1im = ez * sz;
    // f = expm1(z) / A = expm1(z) * conj(A) / |A|^2
    float inv = 1.0f / (are * are + aimv * aimv);
    float fre = (em1re * are + em1im * aimv) * inv;
    float fim = (em1im * are - em1re * aimv) * inv;
    float bre = Bre[i], bim = Bim[i];
    g_dBre[i] = bre * fre - bim * fim;
    g_dBim[i] = bre * fim + bim * fre;
    g_C2re[i]  =  2.0f * Cre[i];
    g_C2imN[i] = -2.0f * Cim[i];
}

// ---------------------------------------------------------------------------
// Scan kernel: 8 lanes per (b,h) scan, 4 modes per lane (two f32x2 pairs),
// 4 scans per warp. 1024 warps total.
// stateMode: 0 = no state write, 1 = real parts only, 2 = planar re then im
// ---------------------------------------------------------------------------
__global__ void __launch_bounds__(256, 4)
s4d_scan_kernel(const float* __restrict__ x,
                const float* __restrict__ Dv,
                float* __restrict__ out,
                int stateMode) {
    const int lane = threadIdx.x & 31;
    const int gw   = blockIdx.x * 8 + (threadIdx.x >> 5);  // global warp id [0,1024)
    const int sub  = lane >> 3;   // scan group within warp (0..3)
    const int j    = lane & 7;    // lane within group: modes 4j..4j+3

    const int hb = gw & 127;          // h-block of 4
    const int b  = gw >> 7;           // batch
    const int h  = hb * 4 + sub;

    // Load per-mode parameters (float4 = 4 consecutive modes)
    const int pb = h * N2 + 4 * j;
    float4 ar = *reinterpret_cast<const float4*>(&g_dAre[pb]);
    float4 ai = *reinterpret_cast<const float4*>(&g_dAim[pb]);
    float4 br = *reinterpret_cast<const float4*>(&g_dBre[pb]);
    float4 bi = *reinterpret_cast<const float4*>(&g_dBim[pb]);
    float4 cr = *reinterpret_cast<const float4*>(&g_C2re[pb]);
    float4 ci = *reinterpret_cast<const float4*>(&g_C2imN[pb]);

    const u64 dAre0 = pk2(ar.x, ar.y), dAre1 = pk2(ar.z, ar.w);
    const u64 dAim0 = pk2(ai.x, ai.y), dAim1 = pk2(ai.z, ai.w);
    const u64 dAimN0 = pk2(-ai.x, -ai.y), dAimN1 = pk2(-ai.z, -ai.w);
    const u64 dBre0 = pk2(br.x, br.y), dBre1 = pk2(br.z, br.w);
    const u64 dBim0 = pk2(bi.x, bi.y), dBim1 = pk2(bi.z, bi.w);
    const u64 C2re0 = pk2(cr.x, cr.y), C2re1 = pk2(cr.z, cr.w);
    const u64 C2imN0 = pk2(ci.x, ci.y), C2imN1 = pk2(ci.z, ci.w);

    const float Dh = Dv[h];

    // state (complex), packed across modes
    u64 sre0 = 0ull, sim0 = 0ull, sre1 = 0ull, sim1 = 0ull;  // 0.0f pairs

    const size_t base = ((size_t)b * Lseq) * Hdim + h;
    const float* __restrict__ xp = x + base;
    float* __restrict__ yp = out + base;

    float xv = __ldg(xp);

    #pragma unroll 4
    for (int t = 0; t < Lseq; ++t) {
        // prefetch next x (wrap keeps address in-bounds on last iter)
        float xn = __ldg(xp + (size_t)((t + 1) & (Lseq - 1)) * Hdim);

        u64 x2 = pk2(xv, xv);

        // state' = dA * state + dB * x   (complex, elementwise over modes)
        u64 nre0 = fma2(dAre0, sre0, fma2(dAimN0, sim0, mul2(dBre0, x2)));
        u64 nim0 = fma2(dAim0, sre0, fma2(dAre0, sim0, mul2(dBim0, x2)));
        u64 nre1 = fma2(dAre1, sre1, fma2(dAimN1, sim1, mul2(dBre1, x2)));
        u64 nim1 = fma2(dAim1, sre1, fma2(dAre1, sim1, mul2(dBim1, x2)));

        // c = sum_n [ 2*C_re*s_re - 2*C_im*s_im ]
        u64 acc = mul2(C2re0, nre0);
        acc = fma2(C2imN0, nim0, acc);
        acc = fma2(C2re1, nre1, acc);
        acc = fma2(C2imN1, nim1, acc);

        sre0 = nre0; sim0 = nim0; sre1 = nre1; sim1 = nim1;

        float2 a = upk2(acc);
        float c = a.x + a.y;
        // reduce across the 8 lanes of this scan group
        c += __shfl_xor_sync(0xffffffffu, c, 1);
        c += __shfl_xor_sync(0xffffffffu, c, 2);
        c += __shfl_xor_sync(0xffffffffu, c, 4);

        float yv = fmaf(Dh, xv, c);
        // exact GELU: 0.5*y*(1+erf(y/sqrt(2)))
        float g = 0.5f * yv * (1.0f + erff(yv * 0.70710678118654752f));

        if (j == 0) yp[(size_t)t * Hdim] = g;
        xv = xn;
    }

    if (stateMode > 0) {
        float2 r0 = upk2(sre0), i0 = upk2(sim0);
        float2 r1 = upk2(sre1), i1 = upk2(sim1);
        const size_t ysEnd = (size_t)Bsz * Lseq * Hdim;      // 16,777,216
        const size_t stN   = (size_t)Bsz * Hdim * N2;        // 131,072
        const size_t idx   = ((size_t)b * Hdim + h) * N2 + 4 * j;
        // Real parts: contiguous (B, H, N2) block right after ys
        float4 vre = make_float4(r0.x, r0.y, r1.x, r1.y);
        reinterpret_cast<float4*>(out + ysEnd + idx)[0] = vre;
        if (stateMode > 1) {
            // Imag parts: second planar block
            float4 vim = make_float4(i0.x, i0.y, i1.x, i1.y);
            reinterpret_cast<float4*>(out + ysEnd + stN + idx)[0] = vim;
        }
    }
}

// ---------------------------------------------------------------------------
// Launch
// ---------------------------------------------------------------------------
extern "C" void kernel_launch(void* const* d_in, const int* in_sizes, int n_in,
                              void* d_out, int out_size) {
    const float* x      = (const float*)d_in[0];
    const float* log_dt = (const float*)d_in[1];
    const float* arl    = (const float*)d_in[2];
    const float* aim    = (const float*)d_in[3];
    const float* Bre    = (const float*)d_in[4];
    const float* Bim    = (const float*)d_in[5];
    const float* Cre    = (const float*)d_in[6];
    const float* Cim    = (const float*)d_in[7];
    const float* Dv     = (const float*)d_in[8];
    float* out = (float*)d_out;

    s4d_precompute<<<(HN + 255) / 256, 256>>>(log_dt, arl, aim, Bre, Bim, Cre, Cim);

    const long long ysElems = (long long)Bsz * Lseq * Hdim;   // 16,777,216
    const long long stN     = (long long)Bsz * Hdim * N2;     // 131,072 modes
    // Decide state layout from available room:
    //   room >= ys + 2*stN : planar re block then im block
    //   room >= ys +   stN : real parts only (complex cast to float32 drops imag)
    int stateMode = 0;
    if ((long long)out_size >= ysElems + 2 * stN) stateMode = 2;
    else if ((long long)out_size >= ysElems + stN) stateMode = 1;

    // 1024 warps: 128 blocks x 256 threads (8 warps/block, 4 scans/warp)
    s4d_scan_kernel<<<128, 256>>>(x, Dv, out, stateMode);
}

// round 5
// speedup vs baseline: 1.8893x; 1.8893x over previous
#include <cuda_runtime.h>
#include <math.h>

// Problem constants
#define Bsz 8
#define Lseq 4096
#define Hdim 512
#define N2 32
#define HN (Hdim * N2)
#define NC 8                 // number of sequence chunks
#define CHUNK (Lseq / NC)    // 512 steps per chunk
#define NWARPS (NC * Bsz * 128)  // warps per pass: 8192 (4 scans per warp)

typedef unsigned long long u64;

// ---------------------------------------------------------------------------
// Packed f32x2 helpers (Blackwell sm_103a)
// ---------------------------------------------------------------------------
__device__ __forceinline__ u64 pk2(float lo, float hi) {
    u64 r;
    asm("mov.b64 %0, {%1, %2};" : "=l"(r) : "f"(lo), "f"(hi));
    return r;
}
__device__ __forceinline__ float2 upk2(u64 v) {
    float2 f;
    asm("mov.b64 {%0, %1}, %2;" : "=f"(f.x), "=f"(f.y) : "l"(v));
    return f;
}
__device__ __forceinline__ u64 fma2(u64 a, u64 b, u64 c) {
    u64 d;
    asm("fma.rn.f32x2 %0, %1, %2, %3;" : "=l"(d) : "l"(a), "l"(b), "l"(c));
    return d;
}
__device__ __forceinline__ u64 mul2(u64 a, u64 b) {
    u64 d;
    asm("mul.rn.f32x2 %0, %1, %2;" : "=l"(d) : "l"(a), "l"(b));
    return d;
}

// ---------------------------------------------------------------------------
// Precomputed parameters and inter-chunk scratch
// ---------------------------------------------------------------------------
__device__ float g_dAre[HN];
__device__ float g_dAim[HN];
__device__ float g_dBre[HN];
__device__ float g_dBim[HN];
__device__ float g_C2re[HN];     //  2 * C_re
__device__ float g_C2imN[HN];    // -2 * C_im
__device__ float g_dA512re[HN];  // dA^CHUNK
__device__ float g_dA512im[HN];

__device__ float g_locre[NC * Bsz * HN];  // chunk-local final states
__device__ float g_locim[NC * Bsz * HN];
__device__ float g_carre[NC * Bsz * HN];  // chunk carry-in states
__device__ float g_carim[NC * Bsz * HN];

// ZOH discretization: dA = exp(dt*A), dB = B * expm1(dt*A)/A, plus dA^CHUNK
__global__ void s4d_precompute(const float* __restrict__ log_dt,
                               const float* __restrict__ arl,
                               const float* __restrict__ aim,
                               const float* __restrict__ Bre,
                               const float* __restrict__ Bim,
                               const float* __restrict__ Cre,
                               const float* __restrict__ Cim) {
    int i = blockIdx.x * blockDim.x + threadIdx.x;
    if (i >= HN) return;
    int h = i / N2;
    float dt   = expf(log_dt[h]);
    float are  = -expf(arl[i]);
    float aimv = aim[i];
    float zre = are * dt;
    float zim = aimv * dt;
    float sz, cz;
    sincosf(zim, &sz, &cz);
    float ez = expf(zre);
    g_dAre[i] = ez * cz;
    g_dAim[i] = ez * sz;
    // expm1(z) = expm1(zre)*cos(zim) - 2 sin^2(zim/2)  + i * e^{zre} sin(zim)
    float sh = sinf(0.5f * zim);
    float em1re = expm1f(zre) * cz - 2.0f * sh * sh;
    float em1im = ez * sz;
    float inv = 1.0f / (are * are + aimv * aimv);
    float fre = (em1re * are + em1im * aimv) * inv;
    float fim = (em1im * are - em1re * aimv) * inv;
    float bre = Bre[i], bim = Bim[i];
    g_dBre[i] = bre * fre - bim * fim;
    g_dBim[i] = bre * fim + bim * fre;
    g_C2re[i]  =  2.0f * Cre[i];
    g_C2imN[i] = -2.0f * Cim[i];
    // dA^CHUNK in double precision: exp(CHUNK * z)
    double zre_d = (double)are * (double)dt * (double)CHUNK;
    double zim_d = (double)aimv * (double)dt * (double)CHUNK;
    double ezd = exp(zre_d);
    g_dA512re[i] = (float)(ezd * cos(zim_d));
    g_dA512im[i] = (float)(ezd * sin(zim_d));
}

// ---------------------------------------------------------------------------
// Pass 1: chunk-local state-only scan (zero init). 8 lanes per scan,
// 4 modes per lane, 4 scans per warp, NWARPS warps.
// ---------------------------------------------------------------------------
__global__ void __launch_bounds__(256, 4)
s4d_pass1(const float* __restrict__ x) {
    const int lane = threadIdx.x & 31;
    const int gw   = blockIdx.x * 8 + (threadIdx.x >> 5);  // [0, NWARPS)
    const int sub  = lane >> 3;
    const int j    = lane & 7;

    const int hb = gw & 127;
    const int b  = (gw >> 7) & 7;
    const int c  = gw >> 10;        // chunk index [0, NC)
    const int h  = hb * 4 + sub;

    const int pb = h * N2 + 4 * j;
    float4 ar = *reinterpret_cast<const float4*>(&g_dAre[pb]);
    float4 ai = *reinterpret_cast<const float4*>(&g_dAim[pb]);
    float4 br = *reinterpret_cast<const float4*>(&g_dBre[pb]);
    float4 bi = *reinterpret_cast<const float4*>(&g_dBim[pb]);

    const u64 dAre0 = pk2(ar.x, ar.y), dAre1 = pk2(ar.z, ar.w);
    const u64 dAim0 = pk2(ai.x, ai.y), dAim1 = pk2(ai.z, ai.w);
    const u64 dAimN0 = pk2(-ai.x, -ai.y), dAimN1 = pk2(-ai.z, -ai.w);
    const u64 dBre0 = pk2(br.x, br.y), dBre1 = pk2(br.z, br.w);
    const u64 dBim0 = pk2(bi.x, bi.y), dBim1 = pk2(bi.z, bi.w);

    u64 sre0 = 0ull, sim0 = 0ull, sre1 = 0ull, sim1 = 0ull;

    const float* __restrict__ xp =
        x + ((size_t)b * Lseq + (size_t)c * CHUNK) * Hdim + h;

    float xv = __ldg(xp);
    #pragma unroll 4
    for (int t = 0; t < CHUNK; ++t) {
        float xn = __ldg(xp + (size_t)((t + 1) & (CHUNK - 1)) * Hdim);
        u64 x2 = pk2(xv, xv);
        u64 nre0 = fma2(dAre0, sre0, fma2(dAimN0, sim0, mul2(dBre0, x2)));
        u64 nim0 = fma2(dAim0, sre0, fma2(dAre0, sim0, mul2(dBim0, x2)));
        u64 nre1 = fma2(dAre1, sre1, fma2(dAimN1, sim1, mul2(dBre1, x2)));
        u64 nim1 = fma2(dAim1, sre1, fma2(dAre1, sim1, mul2(dBim1, x2)));
        sre0 = nre0; sim0 = nim0; sre1 = nre1; sim1 = nim1;
        xv = xn;
    }

    const size_t idx = ((size_t)(c * Bsz + b) * Hdim + h) * N2 + 4 * j;
    float2 r0 = upk2(sre0), i0 = upk2(sim0);
    float2 r1 = upk2(sre1), i1 = upk2(sim1);
    *reinterpret_cast<float4*>(&g_locre[idx]) = make_float4(r0.x, r0.y, r1.x, r1.y);
    *reinterpret_cast<float4*>(&g_locim[idx]) = make_float4(i0.x, i0.y, i1.x, i1.y);
}

// ---------------------------------------------------------------------------
// Carry combine: per (b,h,n), exclusive scan over chunks.
// ---------------------------------------------------------------------------
__global__ void s4d_carry() {
    int i = blockIdx.x * blockDim.x + threadIdx.x;  // [0, Bsz*HN)
    if (i >= Bsz * HN) return;
    int b = i / HN;
    int r = i % HN;  // h*N2 + n
    float a_re = g_dA512re[r], a_im = g_dA512im[r];
    float cre = 0.0f, cim = 0.0f;
    #pragma unroll
    for (int c = 0; c < NC; ++c) {
        size_t idx = (size_t)(c * Bsz + b) * HN + r;
        g_carre[idx] = cre;
        g_carim[idx] = cim;
        float lre = g_locre[idx], lim = g_locim[idx];
        float nre = fmaf(a_re, cre, fmaf(-a_im, cim, lre));
        float nim = fmaf(a_im, cre, fmaf(a_re, cim, lim));
        cre = nre; cim = nim;
    }
}

// ---------------------------------------------------------------------------
// Pass 2: full scan per chunk with carry-in init. Writes ys (+ final state
// from the last chunk). NWARPS warps.
// stateMode: 0 none, 1 real-only, 2 planar re/im
// ---------------------------------------------------------------------------
__global__ void __launch_bounds__(256, 4)
s4d_pass2(const float* __restrict__ x,
          const float* __restrict__ Dv,
          float* __restrict__ out,
          int stateMode) {
    const int lane = threadIdx.x & 31;
    const int gw   = blockIdx.x * 8 + (threadIdx.x >> 5);
    const int sub  = lane >> 3;
    const int j    = lane & 7;

    const int hb = gw & 127;
    const int b  = (gw >> 7) & 7;
    const int c  = gw >> 10;
    const int h  = hb * 4 + sub;

    const int pb = h * N2 + 4 * j;
    float4 ar = *reinterpret_cast<const float4*>(&g_dAre[pb]);
    float4 ai = *reinterpret_cast<const float4*>(&g_dAim[pb]);
    float4 br = *reinterpret_cast<const float4*>(&g_dBre[pb]);
    float4 bi = *reinterpret_cast<const float4*>(&g_dBim[pb]);
    float4 cr = *reinterpret_cast<const float4*>(&g_C2re[pb]);
    float4 ci = *reinterpret_cast<const float4*>(&g_C2imN[pb]);

    const u64 dAre0 = pk2(ar.x, ar.y), dAre1 = pk2(ar.z, ar.w);
    const u64 dAim0 = pk2(ai.x, ai.y), dAim1 = pk2(ai.z, ai.w);
    const u64 dAimN0 = pk2(-ai.x, -ai.y), dAimN1 = pk2(-ai.z, -ai.w);
    const u64 dBre0 = pk2(br.x, br.y), dBre1 = pk2(br.z, br.w);
    const u64 dBim0 = pk2(bi.x, bi.y), dBim1 = pk2(bi.z, bi.w);
    const u64 C2re0 = pk2(cr.x, cr.y), C2re1 = pk2(cr.z, cr.w);
    const u64 C2imN0 = pk2(ci.x, ci.y), C2imN1 = pk2(ci.z, ci.w);

    const float Dh = Dv[h];

    // init state from carry
    const size_t cidx = ((size_t)(c * Bsz + b) * Hdim + h) * N2 + 4 * j;
    float4 crre = *reinterpret_cast<const float4*>(&g_carre[cidx]);
    float4 crim = *reinterpret_cast<const float4*>(&g_carim[cidx]);
    u64 sre0 = pk2(crre.x, crre.y), sre1 = pk2(crre.z, crre.w);
    u64 sim0 = pk2(crim.x, crim.y), sim1 = pk2(crim.z, crim.w);

    const size_t base = ((size_t)b * Lseq + (size_t)c * CHUNK) * Hdim + h;
    const float* __restrict__ xp = x + base;
    float* __restrict__ yp = out + base;

    float xv = __ldg(xp);

    #pragma unroll 4
    for (int t = 0; t < CHUNK; ++t) {
        float xn = __ldg(xp + (size_t)((t + 1) & (CHUNK - 1)) * Hdim);

        u64 x2 = pk2(xv, xv);
        u64 nre0 = fma2(dAre0, sre0, fma2(dAimN0, sim0, mul2(dBre0, x2)));
        u64 nim0 = fma2(dAim0, sre0, fma2(dAre0, sim0, mul2(dBim0, x2)));
        u64 nre1 = fma2(dAre1, sre1, fma2(dAimN1, sim1, mul2(dBre1, x2)));
        u64 nim1 = fma2(dAim1, sre1, fma2(dAre1, sim1, mul2(dBim1, x2)));

        u64 acc = mul2(C2re0, nre0);
        acc = fma2(C2imN0, nim0, acc);
        acc = fma2(C2re1, nre1, acc);
        acc = fma2(C2imN1, nim1, acc);

        sre0 = nre0; sim0 = nim0; sre1 = nre1; sim1 = nim1;

        float2 a = upk2(acc);
        float cc = a.x + a.y;
        cc += __shfl_xor_sync(0xffffffffu, cc, 1);
        cc += __shfl_xor_sync(0xffffffffu, cc, 2);
        cc += __shfl_xor_sync(0xffffffffu, cc, 4);

        float yv = fmaf(Dh, xv, cc);
        float g = 0.5f * yv * (1.0f + erff(yv * 0.70710678118654752f));

        if (j == 0) yp[(size_t)t * Hdim] = g;
        xv = xn;
    }

    if (stateMode > 0 && c == NC - 1) {
        float2 r0 = upk2(sre0), i0 = upk2(sim0);
        float2 r1 = upk2(sre1), i1 = upk2(sim1);
        const size_t ysEnd = (size_t)Bsz * Lseq * Hdim;
        const size_t stN   = (size_t)Bsz * Hdim * N2;
        const size_t idx   = ((size_t)b * Hdim + h) * N2 + 4 * j;
        *reinterpret_cast<float4*>(out + ysEnd + idx) =
            make_float4(r0.x, r0.y, r1.x, r1.y);
        if (stateMode > 1) {
            *reinterpret_cast<float4*>(out + ysEnd + stN + idx) =
                make_float4(i0.x, i0.y, i1.x, i1.y);
        }
    }
}

// ---------------------------------------------------------------------------
// Launch
// ---------------------------------------------------------------------------
extern "C" void kernel_launch(void* const* d_in, const int* in_sizes, int n_in,
                              void* d_out, int out_size) {
    const float* x      = (const float*)d_in[0];
    const float* log_dt = (const float*)d_in[1];
    const float* arl    = (const float*)d_in[2];
    const float* aim    = (const float*)d_in[3];
    const float* Bre    = (const float*)d_in[4];
    const float* Bim    = (const float*)d_in[5];
    const float* Cre    = (const float*)d_in[6];
    const float* Cim    = (const float*)d_in[7];
    const float* Dv     = (const float*)d_in[8];
    float* out = (float*)d_out;

    s4d_precompute<<<(HN + 255) / 256, 256>>>(log_dt, arl, aim, Bre, Bim, Cre, Cim);

    const long long ysElems = (long long)Bsz * Lseq * Hdim;   // 16,777,216
    const long long stN     = (long long)Bsz * Hdim * N2;     // 131,072
    int stateMode = 0;
    if ((long long)out_size >= ysElems + 2 * stN) stateMode = 2;
    else if ((long long)out_size >= ysElems + stN) stateMode = 1;

    // NWARPS=8192 warps per pass, 8 warps per 256-thread block => 1024 blocks
    s4d_pass1<<<NWARPS / 8, 256>>>(x);
    s4d_carry<<<(Bsz * HN + 255) / 256, 256>>>();
    s4d_pass2<<<NWARPS / 8, 256>>>(x, Dv, out, stateMode);
}